// round 1
// baseline (speedup 1.0000x reference)
#include <cuda_runtime.h>

// SSIM loss, B*C=48 images of 512x512 f32.
// Separable 11-tap Gaussian blur (sigma=1.5) done as shared-memory
// horizontal+vertical passes with 4-wide register tiling.
// Gaussian weights are compile-time immediates -> FFMA-imm (rt_SMSP=1).

static constexpr int NIMG = 48;
static constexpr int S    = 512;
static constexpr int T    = 32;   // output tile (T x T)
static constexpr int RIN  = 42;   // input tile rows (T + 10)
static constexpr int PIN  = 43;   // input tile pitch (conflict-free: gcd(43%32=11,32)=1)
static constexpr int PH   = 33;   // h-array pitch (conflict-free)

__device__ double g_part[256];

static __device__ constexpr float W[11] = {
    0.00102838f, 0.00759876f, 0.03600077f, 0.10936066f, 0.21300549f,
    0.26601165f,
    0.21300549f, 0.10936066f, 0.03600077f, 0.00759876f, 0.00102838f
};

__global__ void zero_kernel() { g_part[threadIdx.x] = 0.0; }

__global__ void __launch_bounds__(256) ssim_kernel(
    const float* __restrict__ pred, const float* __restrict__ targ)
{
    __shared__ float sP[RIN * PIN];
    __shared__ float sT[RIN * PIN];
    __shared__ float sH[5][RIN * PH];
    __shared__ float red[8];

    const int tid  = threadIdx.x;
    const int img  = blockIdx.x >> 8;       // 256 tiles per image
    const int tile = blockIdx.x & 255;
    const int oy   = (tile >> 4) * T;
    const int ox   = (tile & 15) * T;

    const float* P = pred + img * (S * S);
    const float* Q = targ + img * (S * S);

    // ---- load input tile (+5 halo each side, zero-padded = SAME padding) ----
    for (int i = tid; i < RIN * PIN; i += 256) {
        int r = i / PIN, c = i - r * PIN;
        int gy = oy + r - 5, gx = ox + c - 5;
        float pv = 0.f, tv = 0.f;
        if ((unsigned)gy < (unsigned)S && (unsigned)gx < (unsigned)S) {
            pv = __ldg(P + gy * S + gx);
            tv = __ldg(Q + gy * S + gx);
        }
        sP[i] = pv;
        sT[i] = tv;
    }
    __syncthreads();

    // ---- horizontal pass: 42 rows x 8 groups of 4 output cols ----
    for (int it = tid; it < RIN * 8; it += 256) {
        int r  = it >> 3;
        int c0 = (it & 7) * 4;
        const float* rp = sP + r * PIN + c0;
        const float* rq = sT + r * PIN + c0;
        float aP[4] = {0, 0, 0, 0}, aT[4] = {0, 0, 0, 0};
        float aPP[4] = {0, 0, 0, 0}, aTT[4] = {0, 0, 0, 0}, aPT[4] = {0, 0, 0, 0};
#pragma unroll
        for (int k = 0; k < 14; ++k) {
            float p = rp[k], q = rq[k];
            float pp = p * p, qq = q * q, pq = p * q;
#pragma unroll
            for (int j = 0; j < 4; ++j) {
                int w = k - j;
                if (w >= 0 && w < 11) {
                    aP[j]  = fmaf(p,  W[w], aP[j]);
                    aT[j]  = fmaf(q,  W[w], aT[j]);
                    aPP[j] = fmaf(pp, W[w], aPP[j]);
                    aTT[j] = fmaf(qq, W[w], aTT[j]);
                    aPT[j] = fmaf(pq, W[w], aPT[j]);
                }
            }
        }
#pragma unroll
        for (int j = 0; j < 4; ++j) {
            sH[0][r * PH + c0 + j] = aP[j];
            sH[1][r * PH + c0 + j] = aT[j];
            sH[2][r * PH + c0 + j] = aPP[j];
            sH[3][r * PH + c0 + j] = aTT[j];
            sH[4][r * PH + c0 + j] = aPT[j];
        }
    }
    __syncthreads();

    // ---- vertical pass + per-pixel SSIM (each thread: 4 rows, 1 col) ----
    const int x  = tid & 31;
    const int y0 = (tid >> 5) * 4;
    float m1[4]  = {0, 0, 0, 0}, m2[4]  = {0, 0, 0, 0};
    float e11[4] = {0, 0, 0, 0}, e22[4] = {0, 0, 0, 0}, e12[4] = {0, 0, 0, 0};
#pragma unroll
    for (int k = 0; k < 14; ++k) {
        int r = y0 + k;
        float v0 = sH[0][r * PH + x];
        float v1 = sH[1][r * PH + x];
        float v2 = sH[2][r * PH + x];
        float v3 = sH[3][r * PH + x];
        float v4 = sH[4][r * PH + x];
#pragma unroll
        for (int j = 0; j < 4; ++j) {
            int w = k - j;
            if (w >= 0 && w < 11) {
                m1[j]  = fmaf(v0, W[w], m1[j]);
                m2[j]  = fmaf(v1, W[w], m2[j]);
                e11[j] = fmaf(v2, W[w], e11[j]);
                e22[j] = fmaf(v3, W[w], e22[j]);
                e12[j] = fmaf(v4, W[w], e12[j]);
            }
        }
    }

    const float C1 = 1e-4f, C2 = 9e-4f, EPSV = 1e-8f;
    float local = 0.f;
#pragma unroll
    for (int j = 0; j < 4; ++j) {
        float a = m1[j], b = m2[j];
        float a2 = a * a, b2 = b * b, ab = a * b;
        float s1  = e11[j] - a2;
        float s2  = e22[j] - b2;
        float s12 = e12[j] - ab;
        float num = (2.f * ab + C1) * (2.f * s12 + C2);
        float den = fmaf(a2 + b2 + C1, s1 + s2 + C2, EPSV);
        local += __fdividef(num, den);
    }

    // ---- block reduction, then 256-slot global accumulation ----
#pragma unroll
    for (int o = 16; o > 0; o >>= 1)
        local += __shfl_down_sync(0xffffffffu, local, o);
    if ((tid & 31) == 0) red[tid >> 5] = local;
    __syncthreads();
    if (tid == 0) {
        float s = 0.f;
#pragma unroll
        for (int i = 0; i < 8; ++i) s += red[i];
        atomicAdd(&g_part[blockIdx.x & 255], (double)s);
    }
}

__global__ void final_kernel(float* out)
{
    __shared__ double sd[256];
    sd[threadIdx.x] = g_part[threadIdx.x];
    __syncthreads();
    for (int s = 128; s > 0; s >>= 1) {
        if (threadIdx.x < s) sd[threadIdx.x] += sd[threadIdx.x + s];
        __syncthreads();
    }
    if (threadIdx.x == 0)
        out[0] = (float)(1.0 - sd[0] / ((double)NIMG * S * S));
}

extern "C" void kernel_launch(void* const* d_in, const int* in_sizes, int n_in,
                              void* d_out, int out_size)
{
    const float* pred = (const float*)d_in[0];
    const float* targ = (const float*)d_in[1];
    float* out = (float*)d_out;

    zero_kernel<<<1, 256>>>();
    ssim_kernel<<<NIMG * 256, 256>>>(pred, targ);
    final_kernel<<<1, 256>>>(out);
}

// round 3
// speedup vs baseline: 2.1968x; 2.1968x over previous
#include <cuda_runtime.h>

// SSIM loss, 48 images of 512x512 f32.
// Separable 11-tap Gaussian blur via shared-memory h+v passes.
// Packed fp32x2 (FFMA2) math: (p,t) and (p^2,t^2) field pairs share one
// packed FMA each; cross term p*t uses scalar FFMA with immediate weight.

static constexpr int NIMG = 48;
static constexpr int S    = 512;
static constexpr int T    = 32;   // output tile (T x T)
static constexpr int RIN  = 42;   // input tile rows (T + 10)
static constexpr int PIN  = 49;   // sPT pitch in float2 (odd -> conflict-free)
static constexpr int PH   = 33;   // sH pitch (odd -> conflict-free)

__device__ double g_part[256];

static __device__ constexpr float W[11] = {
    0.00102838f, 0.00759876f, 0.03600077f, 0.10936066f, 0.21300549f,
    0.26601165f,
    0.21300549f, 0.10936066f, 0.03600077f, 0.00759876f, 0.00102838f
};

__device__ __forceinline__ void ffma2(unsigned long long& d,
                                      unsigned long long a,
                                      unsigned long long b) {
    asm("fma.rn.f32x2 %0, %1, %2, %0;" : "+l"(d) : "l"(a), "l"(b));
}
__device__ __forceinline__ unsigned long long mul2(unsigned long long a,
                                                   unsigned long long b) {
    unsigned long long d;
    asm("mul.rn.f32x2 %0, %1, %2;" : "=l"(d) : "l"(a), "l"(b));
    return d;
}
__device__ __forceinline__ unsigned long long packf2(float lo, float hi) {
    unsigned long long d;
    asm("mov.b64 %0, {%1, %2};" : "=l"(d) : "f"(lo), "f"(hi));
    return d;
}
__device__ __forceinline__ void unpackf2(unsigned long long v, float& lo, float& hi) {
    asm("mov.b64 {%0, %1}, %2;" : "=f"(lo), "=f"(hi) : "l"(v));
}

__global__ void zero_kernel() { g_part[threadIdx.x] = 0.0; }

__global__ void __launch_bounds__(256) ssim_kernel(
    const float* __restrict__ pred, const float* __restrict__ targ)
{
    __shared__ float2 sPT [RIN * PIN];   // interleaved (p, t)
    __shared__ float2 sHmu[RIN * PH];    // (blur_h p, blur_h t)
    __shared__ float2 sHe [RIN * PH];    // (blur_h p^2, blur_h t^2)
    __shared__ float  sH12[RIN * PH];    // blur_h (p*t)
    __shared__ float  red[8];

    const int tid  = threadIdx.x;
    const int img  = blockIdx.x >> 8;
    const int tile = blockIdx.x & 255;
    const int oy   = (tile >> 4) * T;
    const int ox   = (tile & 15) * T;

    const float* P = pred + img * (S * S);
    const float* Q = targ + img * (S * S);

    unsigned long long ww[11];
#pragma unroll
    for (int k = 0; k < 11; ++k) ww[k] = packf2(W[k], W[k]);

    // ---- load: 42 rows x 12 float4 per field; interleave into sPT ----
    // entry e in a row holds global col (ox - 8 + e), e in [0,48)
    for (int i = tid; i < RIN * 12; i += 256) {
        int r   = i / 12;
        int q   = i - r * 12;
        int gy  = oy + r - 5;
        int gx0 = ox + q * 4 - 8;
        float4 p4, t4;
        if (gy >= 0 && gy < S && gx0 >= 0 && gx0 + 3 < S) {
            p4 = *reinterpret_cast<const float4*>(P + gy * S + gx0);
            t4 = *reinterpret_cast<const float4*>(Q + gy * S + gx0);
        } else {
            float pv[4], tv[4];
#pragma unroll
            for (int j = 0; j < 4; ++j) {
                int gx = gx0 + j;
                bool ok = (gy >= 0 && gy < S && gx >= 0 && gx < S);
                pv[j] = ok ? __ldg(P + gy * S + gx) : 0.f;
                tv[j] = ok ? __ldg(Q + gy * S + gx) : 0.f;
            }
            p4 = make_float4(pv[0], pv[1], pv[2], pv[3]);
            t4 = make_float4(tv[0], tv[1], tv[2], tv[3]);
        }
        float2* dst = sPT + r * PIN + q * 4;
        dst[0] = make_float2(p4.x, t4.x);
        dst[1] = make_float2(p4.y, t4.y);
        dst[2] = make_float2(p4.z, t4.z);
        dst[3] = make_float2(p4.w, t4.w);
    }
    __syncthreads();

    // ---- horizontal pass: 42 rows x 8 groups of 4 output cols ----
    // output x needs entries x+3 .. x+13  (entry e <-> gx = ox - 8 + e)
    for (int it = tid; it < RIN * 8; it += 256) {
        int r = it % RIN;              // consecutive lanes -> consecutive rows
        int g = it / RIN;
        int base = r * PIN + g * 4 + 3;
        unsigned long long accA[4] = {0, 0, 0, 0};
        unsigned long long accB[4] = {0, 0, 0, 0};
        float accC[4] = {0, 0, 0, 0};
#pragma unroll
        for (int k = 0; k < 14; ++k) {
            unsigned long long v =
                *reinterpret_cast<const unsigned long long*>(&sPT[base + k]);
            float p, t;
            unpackf2(v, p, t);
            float pt = p * t;
            unsigned long long sq = mul2(v, v);
#pragma unroll
            for (int j = 0; j < 4; ++j) {
                int w = k - j;
                if (w >= 0 && w < 11) {
                    ffma2(accA[j], v,  ww[w]);
                    ffma2(accB[j], sq, ww[w]);
                    accC[j] = fmaf(pt, W[w], accC[j]);
                }
            }
        }
        int ob = r * PH + g * 4;
#pragma unroll
        for (int j = 0; j < 4; ++j) {
            *reinterpret_cast<unsigned long long*>(&sHmu[ob + j]) = accA[j];
            *reinterpret_cast<unsigned long long*>(&sHe [ob + j]) = accB[j];
            sH12[ob + j] = accC[j];
        }
    }
    __syncthreads();

    // ---- vertical pass + SSIM: each thread 4 rows, 1 col ----
    const int x  = tid & 31;
    const int y0 = (tid >> 5) * 4;
    unsigned long long M[4] = {0, 0, 0, 0};
    unsigned long long E[4] = {0, 0, 0, 0};
    float E12[4] = {0, 0, 0, 0};
#pragma unroll
    for (int k = 0; k < 14; ++k) {
        int rr = (y0 + k) * PH + x;
        unsigned long long vm =
            *reinterpret_cast<const unsigned long long*>(&sHmu[rr]);
        unsigned long long ve =
            *reinterpret_cast<const unsigned long long*>(&sHe[rr]);
        float v12 = sH12[rr];
#pragma unroll
        for (int j = 0; j < 4; ++j) {
            int w = k - j;
            if (w >= 0 && w < 11) {
                ffma2(M[j], vm, ww[w]);
                ffma2(E[j], ve, ww[w]);
                E12[j] = fmaf(v12, W[w], E12[j]);
            }
        }
    }

    const float C1 = 1e-4f, C2 = 9e-4f, EPSV = 1e-8f;
    float local = 0.f;
#pragma unroll
    for (int j = 0; j < 4; ++j) {
        float m1, m2, e11, e22;
        unpackf2(M[j], m1, m2);
        unpackf2(E[j], e11, e22);
        float a2 = m1 * m1, b2 = m2 * m2, ab = m1 * m2;
        float s1  = e11 - a2;
        float s2  = e22 - b2;
        float s12 = E12[j] - ab;
        float num = (2.f * ab + C1) * (2.f * s12 + C2);
        float den = fmaf(a2 + b2 + C1, s1 + s2 + C2, EPSV);
        local += __fdividef(num, den);
    }

    // ---- block reduction, then 256-slot global accumulation ----
#pragma unroll
    for (int o = 16; o > 0; o >>= 1)
        local += __shfl_down_sync(0xffffffffu, local, o);
    if ((tid & 31) == 0) red[tid >> 5] = local;
    __syncthreads();
    if (tid == 0) {
        float s = 0.f;
#pragma unroll
        for (int i = 0; i < 8; ++i) s += red[i];
        atomicAdd(&g_part[blockIdx.x & 255], (double)s);
    }
}

__global__ void final_kernel(float* out)
{
    __shared__ double sd[256];
    sd[threadIdx.x] = g_part[threadIdx.x];
    __syncthreads();
    for (int s = 128; s > 0; s >>= 1) {
        if (threadIdx.x < s) sd[threadIdx.x] += sd[threadIdx.x + s];
        __syncthreads();
    }
    if (threadIdx.x == 0)
        out[0] = (float)(1.0 - sd[0] / ((double)NIMG * S * S));
}

extern "C" void kernel_launch(void* const* d_in, const int* in_sizes, int n_in,
                              void* d_out, int out_size)
{
    const float* pred = (const float*)d_in[0];
    const float* targ = (const float*)d_in[1];
    float* out = (float*)d_out;

    zero_kernel<<<1, 256>>>();
    ssim_kernel<<<NIMG * 256, 256>>>(pred, targ);
    final_kernel<<<1, 256>>>(out);
}